// round 11
// baseline (speedup 1.0000x reference)
#include <cuda_runtime.h>
#include <math.h>

#define BN   512     // B*N
#define FEAT 384
#define FFN  768
#define ZD   384
#define HID  192
#define NB   4
#define NN   128
#define LN_EPS 1e-5f
#define XLD  388     // padded smem row stride (floats)

typedef unsigned long long ull;

// ---------------- scratch (device globals; no allocation) ----------------
__device__ __align__(16) float g_xh[BN * ZD];   // gelu'd first half
__device__ __align__(16) float g_z[BN * ZD];    // RAW gelu second half (LN in k2)
__device__ __align__(16) float g_c0[ZD];
__device__ __align__(16) float g_T[NB * ZD];    // sum_j e_off[j] * xh[b,j,:]
__device__ float g_diag[BN];
__device__ float g_off[BN];
__device__ float g_eo[BN];
__device__ float g_wd[BN];
__device__ float g_rD[BN];

__device__ __forceinline__ float gelu_exact(float x) {
    return 0.5f * x * (1.0f + erff(x * 0.70710678118654752440f));
}
// packed f32x2 helpers (sm_103a)
__device__ __forceinline__ ull dup2(float x) {
    ull r; asm("mov.b64 %0, {%1, %1};" : "=l"(r) : "f"(x)); return r;
}
__device__ __forceinline__ void fma2(ull &d, ull a, ull b) {
    asm("fma.rn.f32x2 %0, %1, %2, %0;" : "+l"(d) : "l"(a), "l"(b));
}
__device__ __forceinline__ float2 unp2(ull v) {
    float2 f; asm("mov.b64 {%0, %1}, %2;" : "=f"(f.x), "=f"(f.y) : "l"(v)); return f;
}

// ---------------- k1: h = gelu(x @ U_w + U_b), tile 8 rows x 128 cols -----
// grid 385: bid<384 -> rt=bid/6 (8-row), ct=bid%6 (128-col of 768); bid==384 -> c0
// block 128: cg=t%32 (4 cols), kq=t/32 (4 slices of 96 k); each thread ALL 8 rows.
__global__ __launch_bounds__(128, 8)
void k1_gemmU(const float* __restrict__ x,
              const float* __restrict__ U_w,
              const float* __restrict__ U_b,
              const float* __restrict__ enc_b,
              const float* __restrict__ dec_w,
              const float* __restrict__ dec_b) {
    const int t = threadIdx.x;
    if (blockIdx.x == 384) {
        __shared__ float gh[HID];
        for (int i = t; i < HID; i += 128) gh[i] = gelu_exact(enc_b[i]);
        __syncthreads();
        for (int o = t; o < ZD; o += 128) {
            float acc = dec_b[o];
            for (int ub = 0; ub < HID; ub += 8) {
                float w[8];
#pragma unroll
                for (int i = 0; i < 8; i++) w[i] = dec_w[(ub + i) * ZD + o];
#pragma unroll
                for (int i = 0; i < 8; i++) acc += gh[ub + i] * w[i];
            }
            g_c0[o] = acc;
        }
        return;
    }
    const int rt  = blockIdx.x / 6;
    const int ct  = blockIdx.x % 6;
    const int r0  = rt * 8;
    const int gc0 = ct * 128;

    __shared__ float xs[8 * XLD];         // 12.4 KB
    __shared__ float par[4 * 8 * 128];    // 16 KB

    // stage x tile: 8 rows x 384 k = 768 float4, 6 per thread
#pragma unroll
    for (int i = 0; i < 6; i++) {
        int f4 = t + i * 128;
        int r = f4 / 96, kk = (f4 % 96) * 4;
        *(float4*)&xs[r * XLD + kk] = *(const float4*)(x + (size_t)(r0 + r) * FEAT + kk);
    }
    __syncthreads();

    const int cg = t & 31;
    const int kq = t >> 5;
    const int cc = cg * 4;

    ull acc[8][2] = {};
    const float* wb = U_w + (size_t)(kq * 96) * FFN + gc0 + cc;
    for (int kb = 0; kb < 96; kb += 4) {
        ulonglong2 w[4];
#pragma unroll
        for (int i = 0; i < 4; i++)
            w[i] = *(const ulonglong2*)(wb + (size_t)(kb + i) * FFN);
#pragma unroll
        for (int i = 0; i < 4; i++) {
            const int k = kq * 96 + kb + i;
#pragma unroll
            for (int r = 0; r < 8; r++) {
                ull xp = dup2(xs[r * XLD + k]);
                fma2(acc[r][0], w[i].x, xp);
                fma2(acc[r][1], w[i].y, xp);
            }
        }
    }
#pragma unroll
    for (int r = 0; r < 8; r++) {
        float2 p0 = unp2(acc[r][0]), p1 = unp2(acc[r][1]);
        *(float4*)&par[(kq * 8 + r) * 128 + cc] = make_float4(p0.x, p0.y, p1.x, p1.y);
    }
    __syncthreads();

    // reduce 4 kq partials + bias + gelu + store: 1024 outputs, 8/thread
#pragma unroll
    for (int i = 0; i < 8; i++) {
        int idx = t + i * 128;
        int r = idx >> 7, c = idx & 127;
        float v = par[r * 128 + c] + par[(8 + r) * 128 + c]
                + par[(16 + r) * 128 + c] + par[(24 + r) * 128 + c] + U_b[gc0 + c];
        v = gelu_exact(v);
        int gcol = gc0 + c;
        if (gcol < ZD) g_xh[(size_t)(r0 + r) * ZD + gcol] = v;
        else           g_z[(size_t)(r0 + r) * ZD + gcol - ZD] = v;
    }
}

// ---------------- k2: LN + AE diag + dots, 4-row tiles --------------------
__global__ __launch_bounds__(384, 1)
void k2_ae(const float* __restrict__ enc_w,
           const float* __restrict__ enc_b,
           const float* __restrict__ dec_w,
           const float* __restrict__ dec_b,
           const float* __restrict__ ln_w,
           const float* __restrict__ ln_b) {
    const int r0 = blockIdx.x * 4;
    const int t  = threadIdx.x;
    __shared__ float zs[4 * XLD];
    __shared__ float par[6144];
    __shared__ float hs[4][HID];
    __shared__ float rs1[4][12], rs2[4][12], mu_s[4], rsd_s[4];
    __shared__ float redd[4][12], redo[4][12];

    {
        int r = t / 96, kk = (t % 96) * 4;
        *(float4*)&zs[r * XLD + kk] = *(const float4*)(g_z + (size_t)(r0 + r) * ZD + kk);
    }
    __syncthreads();

    // ---- LayerNorm ----
    const int wI = t >> 5, l = t & 31;
    float v[4];
#pragma unroll
    for (int r = 0; r < 4; r++) {
        v[r] = zs[r * XLD + t];
        float s = v[r], q = v[r] * v[r];
#pragma unroll
        for (int o = 16; o > 0; o >>= 1) {
            s += __shfl_down_sync(0xffffffffu, s, o);
            q += __shfl_down_sync(0xffffffffu, q, o);
        }
        if (l == 0) { rs1[r][wI] = s; rs2[r][wI] = q; }
    }
    __syncthreads();
    if (t < 4) {
        float s = 0.f, q = 0.f;
#pragma unroll
        for (int i = 0; i < 12; i++) { s += rs1[t][i]; q += rs2[t][i]; }
        float mu  = s * (1.0f / ZD);
        float var = q * (1.0f / ZD) - mu * mu;
        mu_s[t]  = mu;
        rsd_s[t] = rsqrtf(var + LN_EPS);
    }
    __syncthreads();
    {
        const float lw = ln_w[t], lb = ln_b[t];
#pragma unroll
        for (int r = 0; r < 4; r++)
            zs[r * XLD + t] = (v[r] - mu_s[r]) * rsd_s[r] * lw + lb;
    }
    __syncthreads();

    // ---- encoder GEMM: cg=t%48 (4 cols), kq=t/48 (8 slices of 48 k) ----
    {
        const int cg = t % 48, kq = t / 48, cc = cg * 4;
        ull accP[4][2] = {};
        const float* wb = enc_w + (size_t)(kq * 48) * HID + cc;
        for (int kb = 0; kb < 48; kb += 8) {
            ulonglong2 w[8];
#pragma unroll
            for (int i = 0; i < 8; i++)
                w[i] = *(const ulonglong2*)(wb + (size_t)(kb + i) * HID);
#pragma unroll
            for (int i = 0; i < 8; i++) {
                const int k = kq * 48 + kb + i;
#pragma unroll
                for (int r = 0; r < 4; r++) {
                    ull zp = dup2(zs[r * XLD + k]);
                    fma2(accP[r][0], w[i].x, zp);
                    fma2(accP[r][1], w[i].y, zp);
                }
            }
        }
#pragma unroll
        for (int r = 0; r < 4; r++) {
            float2 p0 = unp2(accP[r][0]), p1 = unp2(accP[r][1]);
            *(float4*)&par[kq * 768 + r * HID + cc] = make_float4(p0.x, p0.y, p1.x, p1.y);
        }
    }
    __syncthreads();
#pragma unroll
    for (int i = 0; i < 2; i++) {
        int idx = t + i * 384;
        int r = idx / HID, c = idx % HID;
        float h = enc_b[c];
#pragma unroll
        for (int q = 0; q < 8; q++) h += par[q * 768 + r * HID + c];
        hs[r][c] = gelu_exact(h);
    }
    __syncthreads();

    // ---- decoder GEMM: cg=t%96 (4 cols), kq=t/96 (4 slices of 48 u) ----
    {
        const int cg = t % 96, kq = t / 96, cc = cg * 4;
        ull accP[4][2] = {};
        const float* wb = dec_w + (size_t)(kq * 48) * ZD + cc;
        for (int ub = 0; ub < 48; ub += 8) {
            ulonglong2 w[8];
#pragma unroll
            for (int i = 0; i < 8; i++)
                w[i] = *(const ulonglong2*)(wb + (size_t)(ub + i) * ZD);
#pragma unroll
            for (int i = 0; i < 8; i++) {
                const int u = kq * 48 + ub + i;
#pragma unroll
                for (int r = 0; r < 4; r++) {
                    ull hp = dup2(hs[r][u]);
                    fma2(accP[r][0], w[i].x, hp);
                    fma2(accP[r][1], w[i].y, hp);
                }
            }
        }
#pragma unroll
        for (int r = 0; r < 4; r++) {
            float2 p0 = unp2(accP[r][0]), p1 = unp2(accP[r][1]);
            *(float4*)&par[kq * 1536 + r * ZD + cc] = make_float4(p0.x, p0.y, p1.x, p1.y);
        }
    }
    __syncthreads();

    // ---- reduce + dots ----
    const float db = dec_b[t];
    const float c0f = g_c0[t];
    float d[4], o[4];
#pragma unroll
    for (int r = 0; r < 4; r++) {
        float p = par[r * ZD + t] + par[1536 + r * ZD + t]
                + par[3072 + r * ZD + t] + par[4608 + r * ZD + t] + db;
        float zv = zs[r * XLD + t];
        d[r] = p * zv;
        o[r] = c0f * zv;
    }
#pragma unroll
    for (int r = 0; r < 4; r++) {
        float dd = d[r], oo = o[r];
#pragma unroll
        for (int s = 16; s > 0; s >>= 1) {
            dd += __shfl_down_sync(0xffffffffu, dd, s);
            oo += __shfl_down_sync(0xffffffffu, oo, s);
        }
        if (l == 0) { redd[r][wI] = dd; redo[r][wI] = oo; }
    }
    __syncthreads();
    if (t < 4) {
        float dd = 0.f, oo = 0.f;
#pragma unroll
        for (int i = 0; i < 12; i++) { dd += redd[t][i]; oo += redo[t][i]; }
        g_diag[r0 + t] = dd;
        g_off[r0 + t]  = oo;
    }
}

// ---------------- k3: softmax stats + T aggregation (4 blocks x 384) ------
__global__ void k3_stats() {
    const int b = blockIdx.x;
    const int t = threadIdx.x;            // 0..383
    __shared__ float eo_s[NN];
    __shared__ float red[5];
    const int w = t >> 5, l = t & 31;
    float off = 0.f, dg = 0.f, a = 0.f;
    if (t < NN) {
        off = g_off[b * NN + t];
        dg  = g_diag[b * NN + t];
        float m = fmaxf(off, dg);
#pragma unroll
        for (int o = 16; o > 0; o >>= 1) m = fmaxf(m, __shfl_down_sync(0xffffffffu, m, o));
        if (l == 0) red[w] = m;
    }
    __syncthreads();
    if (t == 0) red[4] = fmaxf(fmaxf(red[0], red[1]), fmaxf(red[2], red[3]));
    __syncthreads();
    if (t < NN) {
        float m = red[4];
        a = expf(off - m);
        float c = expf(dg - m);
        eo_s[t] = a;
        g_wd[b * NN + t] = c - a;
        float e1 = a;
#pragma unroll
        for (int o = 16; o > 0; o >>= 1) e1 += __shfl_down_sync(0xffffffffu, e1, o);
        if (l == 0) red[w] = e1;
        // stash c for rD after S known: recompute below via eo_s + wd
    }
    __syncthreads();
    if (t == 0) red[4] = red[0] + red[1] + red[2] + red[3];
    __syncthreads();
    if (t < NN) {
        float S = red[4];
        g_eo[b * NN + t] = a;
        // c - a = wd (already stored); S - a + c = S + wd
        g_rD[b * NN + t] = 1.0f / (S + g_wd[b * NN + t]);
    }
    // T[t] = sum_j eo[j] * xh[b,j,t], batched 16-deep
    float T = 0.f;
    const float* xh = g_xh + (size_t)b * NN * ZD + t;
    for (int jb = 0; jb < NN; jb += 16) {
        float xv[16];
#pragma unroll
        for (int i = 0; i < 16; i++) xv[i] = xh[(size_t)(jb + i) * ZD];
#pragma unroll
        for (int i = 0; i < 16; i++) T += eo_s[jb + i] * xv[i];
    }
    g_T[b * ZD + t] = T;
}

// ---------------- k4: combine + final GEMM, tile 4 rows x 128 cols --------
// grid 384: rt=bid/3 (4-row), ct=bid%3 (128-col of 384)
// block 128: cg=t%32 (4 cols), kq=t/32 (4 slices of 96 f); ALL 4 rows/thread
__global__ __launch_bounds__(128, 8)
void k4_out(const float* __restrict__ V_w,
            const float* __restrict__ V_b,
            float* __restrict__ out) {
    const int rt = blockIdx.x / 3;
    const int ct = blockIdx.x % 3;
    const int r0 = rt * 4;
    const int c0 = ct * 128;
    const int t  = threadIdx.x;
    const int b  = r0 / NN;

    __shared__ float us[4 * XLD];         // 6.2 KB
    __shared__ float par[4 * 4 * 128];    // 8 KB
    __shared__ float wd[4], rd[4];
    if (t < 4) { wd[t] = g_wd[r0 + t]; rd[t] = g_rD[r0 + t]; }
    __syncthreads();

    // us rows: 3 cols per thread
#pragma unroll
    for (int i = 0; i < 3; i++) {
        int c = t + i * 128;
        float Tv = g_T[b * ZD + c];
        float x0 = g_xh[(size_t)(r0 + 0) * ZD + c];
        float x1 = g_xh[(size_t)(r0 + 1) * ZD + c];
        float x2 = g_xh[(size_t)(r0 + 2) * ZD + c];
        float x3 = g_xh[(size_t)(r0 + 3) * ZD + c];
        us[0 * XLD + c] = (Tv + wd[0] * x0) * rd[0];
        us[1 * XLD + c] = (Tv + wd[1] * x1) * rd[1];
        us[2 * XLD + c] = (Tv + wd[2] * x2) * rd[2];
        us[3 * XLD + c] = (Tv + wd[3] * x3) * rd[3];
    }
    __syncthreads();

    const int cg = t & 31;
    const int kq = t >> 5;
    const int cc = cg * 4;
    ull acc[4][2] = {};
    const float* wb = V_w + (size_t)(kq * 96) * FEAT + c0 + cc;
    for (int fb = 0; fb < 96; fb += 4) {
        ulonglong2 w[4];
#pragma unroll
        for (int i = 0; i < 4; i++)
            w[i] = *(const ulonglong2*)(wb + (size_t)(fb + i) * FEAT);
#pragma unroll
        for (int i = 0; i < 4; i++) {
            const int f = kq * 96 + fb + i;
#pragma unroll
            for (int r = 0; r < 4; r++) {
                ull up = dup2(us[r * XLD + f]);
                fma2(acc[r][0], w[i].x, up);
                fma2(acc[r][1], w[i].y, up);
            }
        }
    }
#pragma unroll
    for (int r = 0; r < 4; r++) {
        float2 p0 = unp2(acc[r][0]), p1 = unp2(acc[r][1]);
        *(float4*)&par[(kq * 4 + r) * 128 + cc] = make_float4(p0.x, p0.y, p1.x, p1.y);
    }
    __syncthreads();

    // 512 outputs, 4/thread
#pragma unroll
    for (int i = 0; i < 4; i++) {
        int idx = t + i * 128;
        int r = idx >> 7, c = idx & 127;
        out[(size_t)(r0 + r) * FEAT + c0 + c] =
            par[r * 128 + c] + par[(4 + r) * 128 + c]
          + par[(8 + r) * 128 + c] + par[(12 + r) * 128 + c] + V_b[c0 + c];
    }
}

// ---------------- launch ---------------------------------------------------
extern "C" void kernel_launch(void* const* d_in, const int* in_sizes, int n_in,
                              void* d_out, int out_size) {
    const float* x     = (const float*)d_in[0];
    const float* U_w   = (const float*)d_in[1];
    const float* U_b   = (const float*)d_in[2];
    const float* ln_w  = (const float*)d_in[3];
    const float* ln_b  = (const float*)d_in[4];
    const float* enc_w = (const float*)d_in[5];
    const float* enc_b = (const float*)d_in[6];
    const float* dec_w = (const float*)d_in[7];
    const float* dec_b = (const float*)d_in[8];
    const float* V_w   = (const float*)d_in[9];
    const float* V_b   = (const float*)d_in[10];
    float* out = (float*)d_out;

    k1_gemmU<<<385, 128>>>(x, U_w, U_b, enc_b, dec_w, dec_b);
    k2_ae<<<128, 384>>>(enc_w, enc_b, dec_w, dec_b, ln_w, ln_b);
    k3_stats<<<NB, 384>>>();
    k4_out<<<384, 128>>>(V_w, V_b, out);
}

// round 12
// speedup vs baseline: 1.2362x; 1.2362x over previous
#include <cuda_runtime.h>
#include <math.h>

#define BN   512     // B*N
#define FEAT 384
#define FFN  768
#define ZD   384
#define HID  192
#define NB   4
#define NN   128
#define LN_EPS 1e-5f
#define XLD  388     // padded smem row stride for k2 (floats)

typedef unsigned long long ull;

// ---------------- scratch (device globals; no allocation) ----------------
__device__ __align__(16) float g_xh[BN * ZD];   // gelu'd first half
__device__ __align__(16) float g_z[BN * ZD];    // RAW gelu second half (LN in k2)
__device__ __align__(16) float g_c0[ZD];
__device__ __align__(16) float g_T[NB * ZD];    // sum_j e_off[j] * xh[b,j,:]
__device__ float g_diag[BN];
__device__ float g_off[BN];
__device__ float g_eo[BN];
__device__ float g_wd[BN];
__device__ float g_rD[BN];

__device__ __forceinline__ float gelu_exact(float x) {
    return 0.5f * x * (1.0f + erff(x * 0.70710678118654752440f));
}
// packed f32x2 helpers (sm_103a)
__device__ __forceinline__ ull dup2(float x) {
    ull r; asm("mov.b64 %0, {%1, %1};" : "=l"(r) : "f"(x)); return r;
}
__device__ __forceinline__ void fma2(ull &d, ull a, ull b) {
    asm("fma.rn.f32x2 %0, %1, %2, %0;" : "+l"(d) : "l"(a), "l"(b));
}
__device__ __forceinline__ float2 unp2(ull v) {
    float2 f; asm("mov.b64 {%0, %1}, %2;" : "=f"(f.x), "=f"(f.y) : "l"(v)); return f;
}

// ---------------- k1: h = gelu(x @ U_w + U_b), tile 16 rows x 128 cols ----
// grid 193: bid<192 -> rt=bid/6 (16-row), ct=bid%6 (128-col of 768); bid==192 -> c0
// block 256: cg=t&63 (2 cols), kq=t>>6 (4 slices of 96 k); thread owns ALL 16 rows
// rows packed pairwise into f32x2 lanes; weights broadcast via dup2.
#define K1S 18       // xs2 stride per k (16 rows + pad, even for 8B-aligned ull reads)
__global__ __launch_bounds__(256, 2)
void k1_gemmU(const float* __restrict__ x,
              const float* __restrict__ U_w,
              const float* __restrict__ U_b,
              const float* __restrict__ enc_b,
              const float* __restrict__ dec_w,
              const float* __restrict__ dec_b) {
    const int t = threadIdx.x;
    if (blockIdx.x == 192) {
        __shared__ float gh[HID];
        for (int i = t; i < HID; i += 256) gh[i] = gelu_exact(enc_b[i]);
        __syncthreads();
        for (int o = t; o < ZD; o += 256) {
            float acc = dec_b[o];
            for (int ub = 0; ub < HID; ub += 8) {
                float w[8];
#pragma unroll
                for (int i = 0; i < 8; i++) w[i] = dec_w[(ub + i) * ZD + o];
#pragma unroll
                for (int i = 0; i < 8; i++) acc += gh[ub + i] * w[i];
            }
            g_c0[o] = acc;
        }
        return;
    }
    const int rt  = blockIdx.x / 6;
    const int ct  = blockIdx.x % 6;
    const int r0  = rt * 16;
    const int gc0 = ct * 128;

    __shared__ float sbuf[8192];          // 32 KB: xs2 (384*18=6912), then par (4*16*128)

    // stage x: xs2[k*K1S + row] = x[r0+row][k]; coalesced reads, stride-18 writes
#pragma unroll
    for (int i = 0; i < 24; i++) {
        int e = t + i * 256;              // e < 6144
        int k = e % 384, row = e / 384;
        sbuf[k * K1S + row] = x[(size_t)(r0 + row) * FEAT + k];
    }
    __syncthreads();

    const int cg = t & 63;                // 2 cols: cc, cc+1
    const int kq = t >> 6;                // 4 slices of 96 k
    const int cc = cg * 2;

    ull acc[2][8] = {};                   // [col][rowpair]
    const float* wb = U_w + (size_t)(kq * 96) * FFN + gc0 + cc;
    for (int kb = 0; kb < 96; kb += 8) {
        float2 w[8];
#pragma unroll
        for (int i = 0; i < 8; i++)
            w[i] = *(const float2*)(wb + (size_t)(kb + i) * FFN);
#pragma unroll
        for (int i = 0; i < 8; i++) {
            const int k = kq * 96 + kb + i;
            ull w0 = dup2(w[i].x), w1 = dup2(w[i].y);
            const float* xp = &sbuf[k * K1S];
#pragma unroll
            for (int rp = 0; rp < 8; rp++) {
                ull xv = *(const ull*)(xp + 2 * rp);   // rows 2rp,2rp+1 (broadcast)
                fma2(acc[0][rp], w0, xv);
                fma2(acc[1][rp], w1, xv);
            }
        }
    }
    __syncthreads();   // xs2 reads done; reuse sbuf for partials [kq][row][col]
#pragma unroll
    for (int rp = 0; rp < 8; rp++) {
        float2 p0 = unp2(acc[0][rp]), p1 = unp2(acc[1][rp]);
        sbuf[kq * 2048 + (2 * rp) * 128 + cc]     = p0.x;
        sbuf[kq * 2048 + (2 * rp + 1) * 128 + cc] = p0.y;
        sbuf[kq * 2048 + (2 * rp) * 128 + cc + 1]     = p1.x;
        sbuf[kq * 2048 + (2 * rp + 1) * 128 + cc + 1] = p1.y;
    }
    __syncthreads();

    // reduce 4 kq partials + bias + gelu + store: 2048 outputs, 8/thread
#pragma unroll
    for (int i = 0; i < 8; i++) {
        int idx = t + i * 256;
        int r = idx >> 7, c = idx & 127;
        float v = sbuf[r * 128 + c] + sbuf[2048 + r * 128 + c]
                + sbuf[4096 + r * 128 + c] + sbuf[6144 + r * 128 + c] + U_b[gc0 + c];
        v = gelu_exact(v);
        int gcol = gc0 + c;
        if (gcol < ZD) g_xh[(size_t)(r0 + r) * ZD + gcol] = v;
        else           g_z[(size_t)(r0 + r) * ZD + gcol - ZD] = v;
    }
}

// ---------------- k2: LN + AE diag + dots, 4-row tiles --------------------
__global__ __launch_bounds__(384, 1)
void k2_ae(const float* __restrict__ enc_w,
           const float* __restrict__ enc_b,
           const float* __restrict__ dec_w,
           const float* __restrict__ dec_b,
           const float* __restrict__ ln_w,
           const float* __restrict__ ln_b) {
    const int r0 = blockIdx.x * 4;
    const int t  = threadIdx.x;
    __shared__ float zs[4 * XLD];
    __shared__ float par[6144];
    __shared__ float hs[4][HID];
    __shared__ float rs1[4][12], rs2[4][12], mu_s[4], rsd_s[4];
    __shared__ float redd[4][12], redo[4][12];

    {
        int r = t / 96, kk = (t % 96) * 4;
        *(float4*)&zs[r * XLD + kk] = *(const float4*)(g_z + (size_t)(r0 + r) * ZD + kk);
    }
    __syncthreads();

    // ---- LayerNorm ----
    const int wI = t >> 5, l = t & 31;
    float v[4];
#pragma unroll
    for (int r = 0; r < 4; r++) {
        v[r] = zs[r * XLD + t];
        float s = v[r], q = v[r] * v[r];
#pragma unroll
        for (int o = 16; o > 0; o >>= 1) {
            s += __shfl_down_sync(0xffffffffu, s, o);
            q += __shfl_down_sync(0xffffffffu, q, o);
        }
        if (l == 0) { rs1[r][wI] = s; rs2[r][wI] = q; }
    }
    __syncthreads();
    if (t < 4) {
        float s = 0.f, q = 0.f;
#pragma unroll
        for (int i = 0; i < 12; i++) { s += rs1[t][i]; q += rs2[t][i]; }
        float mu  = s * (1.0f / ZD);
        float var = q * (1.0f / ZD) - mu * mu;
        mu_s[t]  = mu;
        rsd_s[t] = rsqrtf(var + LN_EPS);
    }
    __syncthreads();
    {
        const float lw = ln_w[t], lb = ln_b[t];
#pragma unroll
        for (int r = 0; r < 4; r++)
            zs[r * XLD + t] = (v[r] - mu_s[r]) * rsd_s[r] * lw + lb;
    }
    __syncthreads();

    // ---- encoder GEMM: cg=t%48 (4 cols), kq=t/48 (8 slices of 48 k) ----
    {
        const int cg = t % 48, kq = t / 48, cc = cg * 4;
        ull accP[4][2] = {};
        const float* wb = enc_w + (size_t)(kq * 48) * HID + cc;
        for (int kb = 0; kb < 48; kb += 8) {
            ulonglong2 w[8];
#pragma unroll
            for (int i = 0; i < 8; i++)
                w[i] = *(const ulonglong2*)(wb + (size_t)(kb + i) * HID);
#pragma unroll
            for (int i = 0; i < 8; i++) {
                const int k = kq * 48 + kb + i;
#pragma unroll
                for (int r = 0; r < 4; r++) {
                    ull zp = dup2(zs[r * XLD + k]);
                    fma2(accP[r][0], w[i].x, zp);
                    fma2(accP[r][1], w[i].y, zp);
                }
            }
        }
#pragma unroll
        for (int r = 0; r < 4; r++) {
            float2 p0 = unp2(accP[r][0]), p1 = unp2(accP[r][1]);
            *(float4*)&par[kq * 768 + r * HID + cc] = make_float4(p0.x, p0.y, p1.x, p1.y);
        }
    }
    __syncthreads();
#pragma unroll
    for (int i = 0; i < 2; i++) {
        int idx = t + i * 384;
        int r = idx / HID, c = idx % HID;
        float h = enc_b[c];
#pragma unroll
        for (int q = 0; q < 8; q++) h += par[q * 768 + r * HID + c];
        hs[r][c] = gelu_exact(h);
    }
    __syncthreads();

    // ---- decoder GEMM: cg=t%96 (4 cols), kq=t/96 (4 slices of 48 u) ----
    {
        const int cg = t % 96, kq = t / 96, cc = cg * 4;
        ull accP[4][2] = {};
        const float* wb = dec_w + (size_t)(kq * 48) * ZD + cc;
        for (int ub = 0; ub < 48; ub += 8) {
            ulonglong2 w[8];
#pragma unroll
            for (int i = 0; i < 8; i++)
                w[i] = *(const ulonglong2*)(wb + (size_t)(ub + i) * ZD);
#pragma unroll
            for (int i = 0; i < 8; i++) {
                const int u = kq * 48 + ub + i;
#pragma unroll
                for (int r = 0; r < 4; r++) {
                    ull hp = dup2(hs[r][u]);
                    fma2(accP[r][0], w[i].x, hp);
                    fma2(accP[r][1], w[i].y, hp);
                }
            }
        }
#pragma unroll
        for (int r = 0; r < 4; r++) {
            float2 p0 = unp2(accP[r][0]), p1 = unp2(accP[r][1]);
            *(float4*)&par[kq * 1536 + r * ZD + cc] = make_float4(p0.x, p0.y, p1.x, p1.y);
        }
    }
    __syncthreads();

    // ---- reduce + dots ----
    const float db = dec_b[t];
    const float c0f = g_c0[t];
    float d[4], o[4];
#pragma unroll
    for (int r = 0; r < 4; r++) {
        float p = par[r * ZD + t] + par[1536 + r * ZD + t]
                + par[3072 + r * ZD + t] + par[4608 + r * ZD + t] + db;
        float zv = zs[r * XLD + t];
        d[r] = p * zv;
        o[r] = c0f * zv;
    }
#pragma unroll
    for (int r = 0; r < 4; r++) {
        float dd = d[r], oo = o[r];
#pragma unroll
        for (int s = 16; s > 0; s >>= 1) {
            dd += __shfl_down_sync(0xffffffffu, dd, s);
            oo += __shfl_down_sync(0xffffffffu, oo, s);
        }
        if (l == 0) { redd[r][wI] = dd; redo[r][wI] = oo; }
    }
    __syncthreads();
    if (t < 4) {
        float dd = 0.f, oo = 0.f;
#pragma unroll
        for (int i = 0; i < 12; i++) { dd += redd[t][i]; oo += redo[t][i]; }
        g_diag[r0 + t] = dd;
        g_off[r0 + t]  = oo;
    }
}

// ---------------- k3: softmax stats + T aggregation (4 blocks x 384) ------
__global__ void k3_stats() {
    const int b = blockIdx.x;
    const int t = threadIdx.x;            // 0..383
    __shared__ float eo_s[NN];
    __shared__ float red[5];
    const int w = t >> 5, l = t & 31;
    float off = 0.f, dg = 0.f, a = 0.f;
    if (t < NN) {
        off = g_off[b * NN + t];
        dg  = g_diag[b * NN + t];
        float m = fmaxf(off, dg);
#pragma unroll
        for (int o = 16; o > 0; o >>= 1) m = fmaxf(m, __shfl_down_sync(0xffffffffu, m, o));
        if (l == 0) red[w] = m;
    }
    __syncthreads();
    if (t == 0) red[4] = fmaxf(fmaxf(red[0], red[1]), fmaxf(red[2], red[3]));
    __syncthreads();
    if (t < NN) {
        float m = red[4];
        a = expf(off - m);
        float c = expf(dg - m);
        eo_s[t] = a;
        g_wd[b * NN + t] = c - a;
        float e1 = a;
#pragma unroll
        for (int o = 16; o > 0; o >>= 1) e1 += __shfl_down_sync(0xffffffffu, e1, o);
        if (l == 0) red[w] = e1;
    }
    __syncthreads();
    if (t == 0) red[4] = red[0] + red[1] + red[2] + red[3];
    __syncthreads();
    if (t < NN) {
        float S = red[4];
        g_eo[b * NN + t] = a;
        g_rD[b * NN + t] = 1.0f / (S + g_wd[b * NN + t]);
    }
    // T[t] = sum_j eo[j] * xh[b,j,t], batched 16-deep
    float T = 0.f;
    const float* xh = g_xh + (size_t)b * NN * ZD + t;
    for (int jb = 0; jb < NN; jb += 16) {
        float xv[16];
#pragma unroll
        for (int i = 0; i < 16; i++) xv[i] = xh[(size_t)(jb + i) * ZD];
#pragma unroll
        for (int i = 0; i < 16; i++) T += eo_s[jb + i] * xv[i];
    }
    g_T[b * ZD + t] = T;
}

// ---------------- k4: combine + final GEMM, tile 8 rows x 128 cols --------
// grid 192: rt=bid/3 (8-row), ct=bid%3 (128-col of 384)
// block 256: cg=t&63 (2 cols), kq=t>>6 (4 slices of 96 f); ALL 8 rows/thread
#define K4S 10       // us2 stride per f (8 rows + pad, even)
__global__ __launch_bounds__(256, 2)
void k4_out(const float* __restrict__ V_w,
            const float* __restrict__ V_b,
            float* __restrict__ out) {
    const int rt = blockIdx.x / 3;
    const int ct = blockIdx.x % 3;
    const int r0 = rt * 8;
    const int c0 = ct * 128;
    const int t  = threadIdx.x;
    const int b  = r0 / NN;

    __shared__ float sbuf[4096];          // 16 KB: us2 (384*10=3840), then par (4*8*128)
    __shared__ float wd[8], rd[8];
    if (t < 8) { wd[t] = g_wd[r0 + t]; rd[t] = g_rD[r0 + t]; }
    __syncthreads();

    // stage us2[f*K4S + r] = (T[f] + wd[r]*xh[r0+r][f]) * rd[r]
#pragma unroll
    for (int i = 0; i < 12; i++) {
        int e = t + i * 256;              // e < 3072
        int r = e / 384, f = e % 384;
        sbuf[f * K4S + r] = (g_T[b * ZD + f] + wd[r] * g_xh[(size_t)(r0 + r) * ZD + f]) * rd[r];
    }
    __syncthreads();

    const int cg = t & 63;
    const int kq = t >> 6;
    const int cc = cg * 2;
    ull acc[2][4] = {};                   // [col][rowpair]
    const float* wb = V_w + (size_t)(kq * 96) * FEAT + c0 + cc;
    for (int fb = 0; fb < 96; fb += 8) {
        float2 w[8];
#pragma unroll
        for (int i = 0; i < 8; i++)
            w[i] = *(const float2*)(wb + (size_t)(fb + i) * FEAT);
#pragma unroll
        for (int i = 0; i < 8; i++) {
            const int f = kq * 96 + fb + i;
            ull w0 = dup2(w[i].x), w1 = dup2(w[i].y);
            const float* up = &sbuf[f * K4S];
#pragma unroll
            for (int rp = 0; rp < 4; rp++) {
                ull uv = *(const ull*)(up + 2 * rp);
                fma2(acc[0][rp], w0, uv);
                fma2(acc[1][rp], w1, uv);
            }
        }
    }
    __syncthreads();   // us2 reads done; reuse sbuf for partials [kq][row][col]
#pragma unroll
    for (int rp = 0; rp < 4; rp++) {
        float2 p0 = unp2(acc[0][rp]), p1 = unp2(acc[1][rp]);
        sbuf[kq * 1024 + (2 * rp) * 128 + cc]         = p0.x;
        sbuf[kq * 1024 + (2 * rp + 1) * 128 + cc]     = p0.y;
        sbuf[kq * 1024 + (2 * rp) * 128 + cc + 1]     = p1.x;
        sbuf[kq * 1024 + (2 * rp + 1) * 128 + cc + 1] = p1.y;
    }
    __syncthreads();

    // 1024 outputs, 4/thread
#pragma unroll
    for (int i = 0; i < 4; i++) {
        int idx = t + i * 256;
        int r = idx >> 7, c = idx & 127;
        out[(size_t)(r0 + r) * FEAT + c0 + c] =
            sbuf[r * 128 + c] + sbuf[1024 + r * 128 + c]
          + sbuf[2048 + r * 128 + c] + sbuf[3072 + r * 128 + c] + V_b[c0 + c];
    }
}

// ---------------- launch ---------------------------------------------------
extern "C" void kernel_launch(void* const* d_in, const int* in_sizes, int n_in,
                              void* d_out, int out_size) {
    const float* x     = (const float*)d_in[0];
    const float* U_w   = (const float*)d_in[1];
    const float* U_b   = (const float*)d_in[2];
    const float* ln_w  = (const float*)d_in[3];
    const float* ln_b  = (const float*)d_in[4];
    const float* enc_w = (const float*)d_in[5];
    const float* enc_b = (const float*)d_in[6];
    const float* dec_w = (const float*)d_in[7];
    const float* dec_b = (const float*)d_in[8];
    const float* V_w   = (const float*)d_in[9];
    const float* V_b   = (const float*)d_in[10];
    float* out = (float*)d_out;

    k1_gemmU<<<193, 256>>>(x, U_w, U_b, enc_b, dec_w, dec_b);
    k2_ae<<<128, 384>>>(enc_w, enc_b, dec_w, dec_b, ln_w, ln_b);
    k3_stats<<<NB, 384>>>();
    k4_out<<<192, 256>>>(V_w, V_b, out);
}